// round 9
// baseline (speedup 1.0000x reference)
#include <cuda_runtime.h>
#include <cuda_fp16.h>
#include <cstdint>

#define DEV_INLINE __device__ __forceinline__

constexpr int NN = 8192;   // nodes
constexpr int DF = 256;    // feature dim
constexpr float YSCALE = 4096.f;   // exact pow2: keeps Y out of fp16 subnormals

// ---------------- intermediates (static device globals; no runtime alloc) ----
__device__ float  g_inv_deg[NN];
__device__ __half g_ysTh[(size_t)DF * NN];   // [d][j] = fp16( YSCALE*inv_j*(xW)[j][d] )

// ============================================================================
// helpers (baseline sm_103 ISA only: cp.async, ldmatrix, mma.sync)
// ============================================================================
DEV_INLINE uint32_t smem_u32(const void* p) {
    uint32_t a;
    asm("{ .reg .u64 t; cvta.to.shared.u64 t, %1; cvt.u32.u64 %0, t; }" : "=r"(a) : "l"(p));
    return a;
}
DEV_INLINE void cp16(uint32_t saddr, const void* g) {
    asm volatile("cp.async.cg.shared.global [%0], [%1], 16;" :: "r"(saddr), "l"(g));
}
DEV_INLINE void cp_commit() { asm volatile("cp.async.commit_group;"); }
template <int N> DEV_INLINE void cp_wait() { asm volatile("cp.async.wait_group %0;" :: "n"(N)); }

DEV_INLINE void ldsm4(uint32_t* d, uint32_t addr) {
    asm volatile("ldmatrix.sync.aligned.m8n8.x4.shared.b16 {%0,%1,%2,%3}, [%4];"
                 : "=r"(d[0]), "=r"(d[1]), "=r"(d[2]), "=r"(d[3]) : "r"(addr));
}
DEV_INLINE void mma_f16(float* c, const uint32_t* a, const uint32_t* b) {
    asm volatile(
        "mma.sync.aligned.m16n8k16.row.col.f32.f16.f16.f32 "
        "{%0,%1,%2,%3}, {%4,%5,%6,%7}, {%8,%9}, {%0,%1,%2,%3};"
        : "+f"(c[0]), "+f"(c[1]), "+f"(c[2]), "+f"(c[3])
        : "r"(a[0]), "r"(a[1]), "r"(a[2]), "r"(a[3]), "r"(b[0]), "r"(b[1]));
}
// pack float4 -> two fp16x2 words (memory order preserved)
DEV_INLINE uint2 f4_to_h4(float4 v) {
    union { __half2 h[2]; uint2 u; } p;
    p.h[0] = __floats2half2_rn(v.x, v.y);
    p.h[1] = __floats2half2_rn(v.z, v.w);
    return p.u;
}

// ============================================================================
// Kernel 1: inv_deg[i] = 1/rowsum(A[i,:])   — pure read, 268 MB (~41.5 us)
// ============================================================================
__global__ void __launch_bounds__(256) rowsum_kernel(const float* __restrict__ A) {
    int row = blockIdx.x;
    const float4* r4 = reinterpret_cast<const float4*>(A + (size_t)row * NN);
    float s = 0.f;
#pragma unroll
    for (int it = 0; it < (NN / 4) / 256; it++) {
        float4 v = r4[it * 256 + threadIdx.x];
        s += (v.x + v.y) + (v.z + v.w);
    }
    __shared__ float red[256];
    red[threadIdx.x] = s;
    __syncthreads();
#pragma unroll
    for (int o = 128; o > 0; o >>= 1) {
        if (threadIdx.x < o) red[threadIdx.x] += red[threadIdx.x + o];
        __syncthreads();
    }
    if (threadIdx.x == 0) g_inv_deg[row] = 1.0f / red[0];
}

// ============================================================================
// Kernel 2: ysTh[d][j] = fp16( YSCALE * inv_deg[j] * (x @ W)[j][d] )
// ============================================================================
__global__ void __launch_bounds__(256) xw_kernel(const float* __restrict__ x,
                                                 const float* __restrict__ W) {
    __shared__ float xs[32][DF + 1];
    int r0 = blockIdx.x * 32;
    for (int idx = threadIdx.x; idx < 32 * DF; idx += 256) {
        int r = idx >> 8, c = idx & 255;
        xs[r][c] = x[(size_t)(r0 + r) * DF + c];
    }
    __syncthreads();

    int tx = threadIdx.x & 63;
    int ty = threadIdx.x >> 6;
    float acc[8][4];
#pragma unroll
    for (int r = 0; r < 8; r++)
#pragma unroll
        for (int c = 0; c < 4; c++) acc[r][c] = 0.f;

    const float4* W4 = reinterpret_cast<const float4*>(W);
#pragma unroll 4
    for (int k = 0; k < DF; k++) {
        float4 w = W4[k * 64 + tx];
        float xv[8];
#pragma unroll
        for (int r = 0; r < 8; r++) xv[r] = xs[ty * 8 + r][k];
#pragma unroll
        for (int r = 0; r < 8; r++) {
            acc[r][0] = fmaf(xv[r], w.x, acc[r][0]);
            acc[r][1] = fmaf(xv[r], w.y, acc[r][1]);
            acc[r][2] = fmaf(xv[r], w.z, acc[r][2]);
            acc[r][3] = fmaf(xv[r], w.w, acc[r][3]);
        }
    }
    __syncthreads();
#pragma unroll
    for (int r = 0; r < 8; r++)
#pragma unroll
        for (int c = 0; c < 4; c++) xs[ty * 8 + r][tx * 4 + c] = acc[r][c];
    __syncthreads();

    int d = threadIdx.x;
#pragma unroll
    for (int r = 0; r < 32; r += 4) {
        float s0 = g_inv_deg[r0 + r + 0] * YSCALE;
        float s1 = g_inv_deg[r0 + r + 1] * YSCALE;
        float s2 = g_inv_deg[r0 + r + 2] * YSCALE;
        float s3 = g_inv_deg[r0 + r + 3] * YSCALE;
        union { __half2 h[2]; uint2 u; } p;
        p.h[0] = __floats2half2_rn(xs[r + 0][d] * s0, xs[r + 1][d] * s1);
        p.h[1] = __floats2half2_rn(xs[r + 2][d] * s2, xs[r + 3][d] * s3);
        *reinterpret_cast<uint2*>(&g_ysTh[(size_t)d * NN + r0 + r]) = p.u;
    }
}

// ============================================================================
// Kernel 3: out = relu( (inv_deg_i/YSCALE) * (A @ Yh) + bias )
// Monolithic fp16 mma.sync GEMM with INLINE A conversion:
//   A: LDG.128 fp32 (2-iter register pipeline) -> cvt f16x2 -> STS.64
//   B: fp16 cp.async (unchanged)
// BM=128, BN=128, BK=64, 3-stage smem, 512 threads, grid 64x2 (single wave).
// ============================================================================
constexpr int BM = 128, BN = 128, BK = 64;
constexpr int STAGES = 3;
constexpr int NK = NN / BK;                   // 128
constexpr int ROWH = (BK + 8) * 2;            // 144 B per 64-half row (padded)
constexpr int TILE_B = 128 * ROWH;            // 18432 (A fp16 tile; B identical)
constexpr int STAGE_B = 2 * TILE_B;           // 36864
constexpr int SMEM_GEMM = STAGES * STAGE_B + 2 * BM * 4;   // 111616

__global__ void __launch_bounds__(512, 1) gcn_gemm_kernel(const float* __restrict__ A,
                                                          const float* __restrict__ bias,
                                                          float* __restrict__ out) {
    extern __shared__ char smem[];
    const uint32_t sbase = smem_u32(smem);
    float* invd_s = reinterpret_cast<float*>(smem + STAGES * STAGE_B);
    float* bias_s = invd_s + BM;

    const int tid  = threadIdx.x;
    const int wid  = tid >> 5;
    const int lane = tid & 31;
    const int wm   = wid >> 2;          // 0..3 : 32-row slab
    const int wn   = wid & 3;           // 0..3 : 32-col slab
    const int mbase = blockIdx.x * BM;
    const int nbase = blockIdx.y * BN;

    if (tid < BM) {
        invd_s[tid] = g_inv_deg[mbase + tid] * (1.0f / YSCALE);
        bias_s[tid] = bias[nbase + tid];
    }

    const int g2 = lane >> 2, t2 = lane & 3;
    const int q = lane >> 3, r = lane & 7;
    const uint32_t aoff = (uint32_t)((wm * 32 + (q & 1) * 8 + r) * ROWH + (q >> 1) * 16);
    const uint32_t boff = (uint32_t)((wn * 32 + (q >> 1) * 8 + r) * ROWH + (q & 1) * 16);

    // --- A loader mapping: 4 fp32 16B-chunks per thread per stage
    //     c = i*512 + tid : row = c>>4 (0..127), cq = c&15 (16 chunks x 4 floats)
    int a_row[4], a_cq[4];
#pragma unroll
    for (int i = 0; i < 4; i++) {
        int c = i * 512 + tid;
        a_row[i] = c >> 4;
        a_cq[i]  = c & 15;
    }

    auto ldgA = [&](float4* buf, int kt) {
        const int k0 = kt * BK;
#pragma unroll
        for (int i = 0; i < 4; i++)
            buf[i] = *reinterpret_cast<const float4*>(
                A + (size_t)(mbase + a_row[i]) * NN + k0 + a_cq[i] * 4);
    };
    auto stsA = [&](const float4* buf, int st) {
        const uint32_t sA = sbase + st * STAGE_B;
#pragma unroll
        for (int i = 0; i < 4; i++) {
            uint2 h = f4_to_h4(buf[i]);
            asm volatile("st.shared.v2.u32 [%0], {%1,%2};"
                         :: "r"(sA + a_row[i] * ROWH + a_cq[i] * 8),
                            "r"(h.x), "r"(h.y) : "memory");
        }
    };
    // --- B loader: 1024 fp16 16B chunks via cp.async
    auto loadB = [&](int st, int kt) {
        const uint32_t sB = sbase + st * STAGE_B + TILE_B;
        const int k0 = kt * BK;
#pragma unroll
        for (int i = 0; i < 2; i++) {
            int c = i * 512 + tid;            // 0..1023
            int row = c >> 3, cq = c & 7;
            cp16(sB + row * ROWH + cq * 16,
                 g_ysTh + (size_t)(nbase + row) * NN + k0 + cq * 8);
        }
    };

    float acc[2][4][4];
#pragma unroll
    for (int mt = 0; mt < 2; mt++)
#pragma unroll
        for (int nt = 0; nt < 4; nt++)
#pragma unroll
            for (int i = 0; i < 4; i++) acc[mt][nt][i] = 0.f;

    // --- prologue: A regs for kt=0,1 ; B stages 0,1 in flight
    float4 regA[2][4];
    ldgA(regA[0], 0);
    ldgA(regA[1], 1);
    loadB(0, 0); cp_commit();
    loadB(1, 1); cp_commit();

    int st = 0;
    for (int kt = 0; kt < NK; kt++) {
        // store A(kt) into stage st (stage free: last read at kt-3, fenced at kt-2)
        stsA(regA[kt & 1], st);
        if (kt + 2 < NK) ldgA(regA[kt & 1], kt + 2);   // refill freed buffer

        cp_wait<1>();            // B(kt) resident
        __syncthreads();         // A(kt) STS + B(kt) visible to all

        int pst = st + 2 >= STAGES ? st + 2 - STAGES : st + 2;
        if (kt + 2 < NK) loadB(pst, kt + 2);
        cp_commit();

        const uint32_t sA = sbase + st * STAGE_B;
        const uint32_t sB = sA + TILE_B;
#pragma unroll
        for (int ks = 0; ks < 4; ks++) {       // 4 x k16 steps
            uint32_t afr[2][4];
#pragma unroll
            for (int mt = 0; mt < 2; mt++)
                ldsm4(afr[mt], sA + aoff + mt * (16 * ROWH) + ks * 32);
            uint32_t bfr[2][4];
#pragma unroll
            for (int np = 0; np < 2; np++)
                ldsm4(bfr[np], sB + boff + np * (16 * ROWH) + ks * 32);
#pragma unroll
            for (int mt = 0; mt < 2; mt++)
#pragma unroll
                for (int nt = 0; nt < 4; nt++)
                    mma_f16(acc[mt][nt], afr[mt], &bfr[nt >> 1][(nt & 1) * 2]);
        }
        st = st + 1 >= STAGES ? 0 : st + 1;
    }

    // --- epilogue: scale by inv_deg(row)/YSCALE, add bias, relu, store float2
#pragma unroll
    for (int mt = 0; mt < 2; mt++) {
        const int rl = wm * 32 + mt * 16 + g2;        // local row
        const float s0 = invd_s[rl], s1 = invd_s[rl + 8];
        float* o0 = out + (size_t)(mbase + rl) * DF + nbase + wn * 32;
        float* o1 = o0 + (size_t)8 * DF;
#pragma unroll
        for (int nt = 0; nt < 4; nt++) {
            const int c = nt * 8 + t2 * 2;
            const float b0 = bias_s[wn * 32 + c], b1 = bias_s[wn * 32 + c + 1];
            float2 v0, v1;
            v0.x = fmaxf(fmaf(acc[mt][nt][0], s0, b0), 0.f);
            v0.y = fmaxf(fmaf(acc[mt][nt][1], s0, b1), 0.f);
            v1.x = fmaxf(fmaf(acc[mt][nt][2], s1, b0), 0.f);
            v1.y = fmaxf(fmaf(acc[mt][nt][3], s1, b1), 0.f);
            *reinterpret_cast<float2*>(o0 + c) = v0;
            *reinterpret_cast<float2*>(o1 + c) = v1;
        }
    }
}

// ============================================================================
// Launch
// ============================================================================
extern "C" void kernel_launch(void* const* d_in, const int* in_sizes, int n_in,
                              void* d_out, int out_size) {
    const float* x    = (const float*)d_in[0];   // [8192,256]
    const float* adj  = (const float*)d_in[1];   // [8192,8192]
    const float* W    = (const float*)d_in[2];   // [256,256]
    const float* bias = (const float*)d_in[3];   // [256]
    float* out = (float*)d_out;                  // [8192,256]

    cudaFuncSetAttribute(gcn_gemm_kernel, cudaFuncAttributeMaxDynamicSharedMemorySize,
                         SMEM_GEMM);

    rowsum_kernel<<<NN, 256>>>(adj);
    xw_kernel<<<NN / 32, 256>>>(x, W);
    dim3 grid(NN / BM, DF / BN);   // 64 x 2
    gcn_gemm_kernel<<<grid, 512, SMEM_GEMM>>>(adj, bias, out);
}

// round 10
// speedup vs baseline: 1.3437x; 1.3437x over previous
#include <cuda_runtime.h>
#include <cuda_fp16.h>
#include <cstdint>

#define DEV_INLINE __device__ __forceinline__

constexpr int NN = 8192;   // nodes
constexpr int DF = 256;    // feature dim
constexpr float YSCALE = 4096.f;   // exact pow2: keeps Y out of fp16 subnormals

// ---------------- intermediates (static device globals; no runtime alloc) ----
__device__ float  g_inv_deg[NN];
__device__ __half g_ysTh[(size_t)DF * NN];   // [d][j] = fp16( YSCALE*inv_j*(xW)[j][d] )

// ============================================================================
// helpers (baseline sm_103 ISA only: cp.async, ldmatrix, mma.sync)
// ============================================================================
DEV_INLINE uint32_t smem_u32(const void* p) {
    uint32_t a;
    asm("{ .reg .u64 t; cvta.to.shared.u64 t, %1; cvt.u32.u64 %0, t; }" : "=r"(a) : "l"(p));
    return a;
}
DEV_INLINE void cp16(uint32_t saddr, const void* g) {
    asm volatile("cp.async.cg.shared.global [%0], [%1], 16;" :: "r"(saddr), "l"(g));
}
DEV_INLINE void cp_commit() { asm volatile("cp.async.commit_group;"); }
template <int N> DEV_INLINE void cp_wait() { asm volatile("cp.async.wait_group %0;" :: "n"(N)); }

DEV_INLINE void ldsm4(uint32_t* d, uint32_t addr) {
    asm volatile("ldmatrix.sync.aligned.m8n8.x4.shared.b16 {%0,%1,%2,%3}, [%4];"
                 : "=r"(d[0]), "=r"(d[1]), "=r"(d[2]), "=r"(d[3]) : "r"(addr));
}
DEV_INLINE void mma_f16(float* c, const uint32_t* a, const uint32_t* b) {
    asm volatile(
        "mma.sync.aligned.m16n8k16.row.col.f32.f16.f16.f32 "
        "{%0,%1,%2,%3}, {%4,%5,%6,%7}, {%8,%9}, {%0,%1,%2,%3};"
        : "+f"(c[0]), "+f"(c[1]), "+f"(c[2]), "+f"(c[3])
        : "r"(a[0]), "r"(a[1]), "r"(a[2]), "r"(a[3]), "r"(b[0]), "r"(b[1]));
}

// ============================================================================
// Kernel 1: inv_deg[i] = 1/rowsum(A[i,:])   — pure read, 268 MB (~41.5 us)
// ============================================================================
__global__ void __launch_bounds__(256) rowsum_kernel(const float* __restrict__ A) {
    int row = blockIdx.x;
    const float4* r4 = reinterpret_cast<const float4*>(A + (size_t)row * NN);
    float s = 0.f;
#pragma unroll
    for (int it = 0; it < (NN / 4) / 256; it++) {
        float4 v = r4[it * 256 + threadIdx.x];
        s += (v.x + v.y) + (v.z + v.w);
    }
    __shared__ float red[256];
    red[threadIdx.x] = s;
    __syncthreads();
#pragma unroll
    for (int o = 128; o > 0; o >>= 1) {
        if (threadIdx.x < o) red[threadIdx.x] += red[threadIdx.x + o];
        __syncthreads();
    }
    if (threadIdx.x == 0) g_inv_deg[row] = 1.0f / red[0];
}

// ============================================================================
// Kernel 2: ysTh[d][j] = fp16( YSCALE * inv_deg[j] * (x @ W)[j][d] )
// ============================================================================
__global__ void __launch_bounds__(256) xw_kernel(const float* __restrict__ x,
                                                 const float* __restrict__ W) {
    __shared__ float xs[32][DF + 1];
    int r0 = blockIdx.x * 32;
    for (int idx = threadIdx.x; idx < 32 * DF; idx += 256) {
        int r = idx >> 8, c = idx & 255;
        xs[r][c] = x[(size_t)(r0 + r) * DF + c];
    }
    __syncthreads();

    int tx = threadIdx.x & 63;
    int ty = threadIdx.x >> 6;
    float acc[8][4];
#pragma unroll
    for (int r = 0; r < 8; r++)
#pragma unroll
        for (int c = 0; c < 4; c++) acc[r][c] = 0.f;

    const float4* W4 = reinterpret_cast<const float4*>(W);
#pragma unroll 4
    for (int k = 0; k < DF; k++) {
        float4 w = W4[k * 64 + tx];
        float xv[8];
#pragma unroll
        for (int r = 0; r < 8; r++) xv[r] = xs[ty * 8 + r][k];
#pragma unroll
        for (int r = 0; r < 8; r++) {
            acc[r][0] = fmaf(xv[r], w.x, acc[r][0]);
            acc[r][1] = fmaf(xv[r], w.y, acc[r][1]);
            acc[r][2] = fmaf(xv[r], w.z, acc[r][2]);
            acc[r][3] = fmaf(xv[r], w.w, acc[r][3]);
        }
    }
    __syncthreads();
#pragma unroll
    for (int r = 0; r < 8; r++)
#pragma unroll
        for (int c = 0; c < 4; c++) xs[ty * 8 + r][tx * 4 + c] = acc[r][c];
    __syncthreads();

    int d = threadIdx.x;
#pragma unroll
    for (int r = 0; r < 32; r += 4) {
        float s0 = g_inv_deg[r0 + r + 0] * YSCALE;
        float s1 = g_inv_deg[r0 + r + 1] * YSCALE;
        float s2 = g_inv_deg[r0 + r + 2] * YSCALE;
        float s3 = g_inv_deg[r0 + r + 3] * YSCALE;
        union { __half2 h[2]; uint2 u; } p;
        p.h[0] = __floats2half2_rn(xs[r + 0][d] * s0, xs[r + 1][d] * s1);
        p.h[1] = __floats2half2_rn(xs[r + 2][d] * s2, xs[r + 3][d] * s3);
        *reinterpret_cast<uint2*>(&g_ysTh[(size_t)d * NN + r0 + r]) = p.u;
    }
}

// ============================================================================
// Kernel 3: out = relu( (inv_deg_i/YSCALE) * (A @ Yh) + bias )
// Monolithic fp16 mma.sync GEMM with INLINE A conversion, register-lean:
//   A: LDG.128 fp32 (1-deep 16-reg buffer, issued 1 iter ahead) -> cvt -> STS
//   B: fp16 cp.async
// BM=128, BN=128, BK=64, 3-stage smem, 512 threads, grid 64x2 (single wave).
// ============================================================================
constexpr int BM = 128, BN = 128, BK = 64;
constexpr int STAGES = 3;
constexpr int NK = NN / BK;                   // 128
constexpr int ROWH = (BK + 8) * 2;            // 144 B per 64-half row (padded)
constexpr int TILE_B = 128 * ROWH;            // 18432 (A fp16 tile; B identical)
constexpr int STAGE_B = 2 * TILE_B;           // 36864
constexpr int SMEM_GEMM = STAGES * STAGE_B + 2 * BM * 4;   // 111616

__global__ void __launch_bounds__(512, 1) gcn_gemm_kernel(const float* __restrict__ A,
                                                          const float* __restrict__ bias,
                                                          float* __restrict__ out) {
    extern __shared__ char smem[];
    const uint32_t sbase = smem_u32(smem);
    float* invd_s = reinterpret_cast<float*>(smem + STAGES * STAGE_B);
    float* bias_s = invd_s + BM;

    const int tid  = threadIdx.x;
    const int wid  = tid >> 5;
    const int lane = tid & 31;
    const int wm   = wid >> 2;          // 0..3 : 32-row slab
    const int wn   = wid & 3;           // 0..3 : 32-col slab
    const int mbase = blockIdx.x * BM;
    const int nbase = blockIdx.y * BN;

    if (tid < BM) {
        invd_s[tid] = g_inv_deg[mbase + tid] * (1.0f / YSCALE);
        bias_s[tid] = bias[nbase + tid];
    }

    const int g2 = lane >> 2, t2 = lane & 3;
    const int q = lane >> 3, r = lane & 7;
    const uint32_t aoff = (uint32_t)((wm * 32 + (q & 1) * 8 + r) * ROWH + (q >> 1) * 16);
    const uint32_t boff = (uint32_t)((wn * 32 + (q >> 1) * 8 + r) * ROWH + (q & 1) * 16);

    // A loader: 4 fp32 16B chunks/thread/stage; c = i*512+tid, row=c>>4, cq=c&15
    const float* Abase = A + (size_t)mbase * NN;   // this CTA's 128-row slab

    auto ldgA = [&](float4* buf, int kt) {
        const int k0 = kt * BK;
#pragma unroll
        for (int i = 0; i < 4; i++) {
            int c = i * 512 + tid;
            buf[i] = *reinterpret_cast<const float4*>(
                Abase + (size_t)(c >> 4) * NN + k0 + (c & 15) * 4);
        }
    };
    auto stsA = [&](const float4* buf, int st) {
        const uint32_t sA = sbase + st * STAGE_B;
#pragma unroll
        for (int i = 0; i < 4; i++) {
            int c = i * 512 + tid;
            union { __half2 h[2]; uint2 u; } p;
            p.h[0] = __floats2half2_rn(buf[i].x, buf[i].y);
            p.h[1] = __floats2half2_rn(buf[i].z, buf[i].w);
            asm volatile("st.shared.v2.u32 [%0], {%1,%2};"
                         :: "r"(sA + (c >> 4) * ROWH + (c & 15) * 8),
                            "r"(p.u.x), "r"(p.u.y) : "memory");
        }
    };
    // B loader: 1024 fp16 16B chunks via cp.async
    auto loadB = [&](int st, int kt) {
        const uint32_t sB = sbase + st * STAGE_B + TILE_B;
        const int k0 = kt * BK;
#pragma unroll
        for (int i = 0; i < 2; i++) {
            int c = i * 512 + tid;            // 0..1023
            cp16(sB + (c >> 3) * ROWH + (c & 7) * 16,
                 g_ysTh + (size_t)(nbase + (c >> 3)) * NN + k0 + (c & 7) * 8);
        }
    };

    float acc[2][4][4];
#pragma unroll
    for (int mt = 0; mt < 2; mt++)
#pragma unroll
        for (int nt = 0; nt < 4; nt++)
#pragma unroll
            for (int i = 0; i < 4; i++) acc[mt][nt][i] = 0.f;

    // --- prologue: A regs for kt=0 ; B stages 0,1 in flight
    float4 regA[4];
    ldgA(regA, 0);
    loadB(0, 0); cp_commit();
    loadB(1, 1); cp_commit();

    int st = 0;
    for (int kt = 0; kt < NK; kt++) {
        // convert+store A(kt) into stage st, then immediately refill for kt+1
        stsA(regA, st);
        if (kt + 1 < NK) ldgA(regA, kt + 1);   // WAR on regs: ordered by issue

        cp_wait<1>();            // B(kt) resident
        __syncthreads();         // A(kt) STS + B(kt) visible to all

        int pst = st + 2 >= STAGES ? st + 2 - STAGES : st + 2;
        if (kt + 2 < NK) loadB(pst, kt + 2);
        cp_commit();

        const uint32_t sA = sbase + st * STAGE_B;
        const uint32_t sB = sA + TILE_B;
#pragma unroll
        for (int ks = 0; ks < 4; ks++) {       // 4 x k16 steps
            uint32_t afr[2][4];
#pragma unroll
            for (int mt = 0; mt < 2; mt++)
                ldsm4(afr[mt], sA + aoff + mt * (16 * ROWH) + ks * 32);
            uint32_t bfr[2][4];
#pragma unroll
            for (int np = 0; np < 2; np++)
                ldsm4(bfr[np], sB + boff + np * (16 * ROWH) + ks * 32);
#pragma unroll
            for (int mt = 0; mt < 2; mt++)
#pragma unroll
                for (int nt = 0; nt < 4; nt++)
                    mma_f16(acc[mt][nt], afr[mt], &bfr[nt >> 1][(nt & 1) * 2]);
        }
        st = st + 1 >= STAGES ? 0 : st + 1;
    }

    // --- epilogue: scale by inv_deg(row)/YSCALE, add bias, relu, store float2
#pragma unroll
    for (int mt = 0; mt < 2; mt++) {
        const int rl = wm * 32 + mt * 16 + g2;        // local row
        const float s0 = invd_s[rl], s1 = invd_s[rl + 8];
        float* o0 = out + (size_t)(mbase + rl) * DF + nbase + wn * 32;
        float* o1 = o0 + (size_t)8 * DF;
#pragma unroll
        for (int nt = 0; nt < 4; nt++) {
            const int c = nt * 8 + t2 * 2;
            const float b0 = bias_s[wn * 32 + c], b1 = bias_s[wn * 32 + c + 1];
            float2 v0, v1;
            v0.x = fmaxf(fmaf(acc[mt][nt][0], s0, b0), 0.f);
            v0.y = fmaxf(fmaf(acc[mt][nt][1], s0, b1), 0.f);
            v1.x = fmaxf(fmaf(acc[mt][nt][2], s1, b0), 0.f);
            v1.y = fmaxf(fmaf(acc[mt][nt][3], s1, b1), 0.f);
            *reinterpret_cast<float2*>(o0 + c) = v0;
            *reinterpret_cast<float2*>(o1 + c) = v1;
        }
    }
}

// ============================================================================
// Launch
// ============================================================================
extern "C" void kernel_launch(void* const* d_in, const int* in_sizes, int n_in,
                              void* d_out, int out_size) {
    const float* x    = (const float*)d_in[0];   // [8192,256]
    const float* adj  = (const float*)d_in[1];   // [8192,8192]
    const float* W    = (const float*)d_in[2];   // [256,256]
    const float* bias = (const float*)d_in[3];   // [256]
    float* out = (float*)d_out;                  // [8192,256]

    cudaFuncSetAttribute(gcn_gemm_kernel, cudaFuncAttributeMaxDynamicSharedMemorySize,
                         SMEM_GEMM);

    rowsum_kernel<<<NN, 256>>>(adj);
    xw_kernel<<<NN / 32, 256>>>(x, W);
    dim3 grid(NN / BM, DF / BN);   // 64 x 2
    gcn_gemm_kernel<<<grid, 512, SMEM_GEMM>>>(adj, bias, out);
}

// round 11
// speedup vs baseline: 1.7239x; 1.2829x over previous
#include <cuda_runtime.h>
#include <cuda_fp16.h>
#include <cstdint>

#define DEV_INLINE __device__ __forceinline__

constexpr int NN = 8192;   // nodes
constexpr int DF = 256;    // feature dim
constexpr float YSCALE = 4096.f;   // exact pow2: keeps Y out of fp16 subnormals

// ---------------- intermediates (static device globals; no runtime alloc) ----
__device__ float  g_inv_deg[NN];
__device__ __half g_Ah[(size_t)NN * NN];     // fp16 copy of adjacency (rn)
__device__ __half g_ysTh[(size_t)DF * NN];   // [d][j] = fp16( YSCALE*inv_j*(xW)[j][d] )

// ============================================================================
// helpers (baseline sm_103 ISA only: cp.async, ldmatrix, mma.sync)
// ============================================================================
DEV_INLINE uint32_t smem_u32(const void* p) {
    uint32_t a;
    asm("{ .reg .u64 t; cvta.to.shared.u64 t, %1; cvt.u32.u64 %0, t; }" : "=r"(a) : "l"(p));
    return a;
}
DEV_INLINE void cp16(uint32_t saddr, const void* g) {
    asm volatile("cp.async.cg.shared.global [%0], [%1], 16;" :: "r"(saddr), "l"(g));
}
DEV_INLINE void cp_commit() { asm volatile("cp.async.commit_group;"); }
template <int N> DEV_INLINE void cp_wait() { asm volatile("cp.async.wait_group %0;" :: "n"(N)); }

DEV_INLINE void ldsm4(uint32_t* d, uint32_t addr) {
    asm volatile("ldmatrix.sync.aligned.m8n8.x4.shared.b16 {%0,%1,%2,%3}, [%4];"
                 : "=r"(d[0]), "=r"(d[1]), "=r"(d[2]), "=r"(d[3]) : "r"(addr));
}
DEV_INLINE void ldsm4t(uint32_t* d, uint32_t addr) {
    asm volatile("ldmatrix.sync.aligned.m8n8.x4.trans.shared.b16 {%0,%1,%2,%3}, [%4];"
                 : "=r"(d[0]), "=r"(d[1]), "=r"(d[2]), "=r"(d[3]) : "r"(addr));
}
DEV_INLINE void mma_f16(float* c, const uint32_t* a, const uint32_t* b) {
    asm volatile(
        "mma.sync.aligned.m16n8k16.row.col.f32.f16.f16.f32 "
        "{%0,%1,%2,%3}, {%4,%5,%6,%7}, {%8,%9}, {%0,%1,%2,%3};"
        : "+f"(c[0]), "+f"(c[1]), "+f"(c[2]), "+f"(c[3])
        : "r"(a[0]), "r"(a[1]), "r"(a[2]), "r"(a[3]), "r"(b[0]), "r"(b[1]));
}

// ============================================================================
// Kernel 1: inv_deg[i] = 1/rowsum(A[i,:]); also emits fp16 copy of A.
// ============================================================================
__global__ void __launch_bounds__(256) rowsum_kernel(const float* __restrict__ A) {
    int row = blockIdx.x;
    const float4* r4 = reinterpret_cast<const float4*>(A + (size_t)row * NN);
    __half* ah = g_Ah + (size_t)row * NN;
    float s = 0.f;
#pragma unroll
    for (int it = 0; it < (NN / 4) / 256; it++) {
        int idx = it * 256 + threadIdx.x;
        float4 v = r4[idx];
        s += (v.x + v.y) + (v.z + v.w);
        union { __half2 h[2]; uint2 u; } p;
        p.h[0] = __floats2half2_rn(v.x, v.y);
        p.h[1] = __floats2half2_rn(v.z, v.w);
        *reinterpret_cast<uint2*>(ah + (size_t)idx * 4) = p.u;
    }
    __shared__ float red[256];
    red[threadIdx.x] = s;
    __syncthreads();
#pragma unroll
    for (int o = 128; o > 0; o >>= 1) {
        if (threadIdx.x < o) red[threadIdx.x] += red[threadIdx.x + o];
        __syncthreads();
    }
    if (threadIdx.x == 0) g_inv_deg[row] = 1.0f / red[0];
}

// ============================================================================
// Kernel 2 (tensor-core): ysTh[d][j] = fp16( YSCALE*inv_j * sum_k W[k][d] x[j][k] )
// C[d][j]: A = W^T via ldmatrix.trans (W stored naturally [k][d] in smem),
// B = x (inline fp32->fp16). BM=128(d) x BN=128(j) x BK=64, NK=4, 512 thr.
// Grid (64 j-blocks, 2 d-blocks) = 128 CTAs. Output directly in ysT layout.
// ============================================================================
constexpr int XROWW = (128 + 8) * 2;           // W smem row (k-major): 272 B
constexpr int XROWX = (64 + 8) * 2;            // x smem row: 144 B
constexpr int XW_TILE_W = 64 * XROWW;          // 17408
constexpr int XW_TILE_X = 128 * XROWX;         // 18432
constexpr int SMEM_XW = XW_TILE_W + XW_TILE_X + 128 * 4 + 256;

__global__ void __launch_bounds__(512, 1) xw_tensor_kernel(const float* __restrict__ x,
                                                           const float* __restrict__ W) {
    extern __shared__ char smem[];
    const uint32_t sW = smem_u32(smem);
    const uint32_t sX = sW + XW_TILE_W;
    float* ivd = reinterpret_cast<float*>(smem + XW_TILE_W + XW_TILE_X);

    const int tid  = threadIdx.x;
    const int wid  = tid >> 5;
    const int lane = tid & 31;
    const int wm   = wid >> 2;          // 0..3 : 32 d-rows
    const int wn   = wid & 3;           // 0..3 : 32 j-cols
    const int jbase = blockIdx.x * 128;
    const int dbase = blockIdx.y * 128;

    if (tid < 128) ivd[tid] = g_inv_deg[jbase + tid] * YSCALE;

    const int g2 = lane >> 2, t2 = lane & 3;
    const int q = lane >> 3, r = lane & 7;
    // B (x, non-trans): rows j, 16B chunk per k8
    const uint32_t boff = (uint32_t)((wn * 32 + (q >> 1) * 8 + r) * XROWX + (q & 1) * 16);

    // loaders (fp32 -> fp16, register-staged)
    float4 regW[4], regX[4];
    auto ldgW = [&](int kt) {           // W[k0+kk][dbase + cc*4..+3]
        const int k0 = kt * 64;
#pragma unroll
        for (int i = 0; i < 4; i++) {
            int c = i * 512 + tid;                     // 0..2047
            regW[i] = *reinterpret_cast<const float4*>(
                W + (size_t)(k0 + (c >> 5)) * DF + dbase + (c & 31) * 4);
        }
    };
    auto ldgX = [&](int kt) {           // x[jbase+jj][k0 + cq*4..+3]
        const int k0 = kt * 64;
#pragma unroll
        for (int i = 0; i < 4; i++) {
            int c = i * 512 + tid;                     // 0..2047
            regX[i] = *reinterpret_cast<const float4*>(
                x + (size_t)(jbase + (c >> 4)) * DF + k0 + (c & 15) * 4);
        }
    };
    auto stsAll = [&]() {
#pragma unroll
        for (int i = 0; i < 4; i++) {
            int c = i * 512 + tid;
            union { __half2 h[2]; uint2 u; } p;
            p.h[0] = __floats2half2_rn(regW[i].x, regW[i].y);
            p.h[1] = __floats2half2_rn(regW[i].z, regW[i].w);
            asm volatile("st.shared.v2.u32 [%0], {%1,%2};"
                         :: "r"(sW + (c >> 5) * XROWW + (c & 31) * 8),
                            "r"(p.u.x), "r"(p.u.y) : "memory");
            union { __half2 h[2]; uint2 u; } px;
            px.h[0] = __floats2half2_rn(regX[i].x, regX[i].y);
            px.h[1] = __floats2half2_rn(regX[i].z, regX[i].w);
            asm volatile("st.shared.v2.u32 [%0], {%1,%2};"
                         :: "r"(sX + (c >> 4) * XROWX + (c & 15) * 8),
                            "r"(px.u.x), "r"(px.u.y) : "memory");
        }
    };

    float acc[2][4][4];
#pragma unroll
    for (int mt = 0; mt < 2; mt++)
#pragma unroll
        for (int nt = 0; nt < 4; nt++)
#pragma unroll
            for (int i = 0; i < 4; i++) acc[mt][nt][i] = 0.f;

    ldgW(0); ldgX(0);
    for (int kt = 0; kt < 4; kt++) {
        __syncthreads();                 // previous-iter readers done
        stsAll();
        if (kt + 1 < 4) { ldgW(kt + 1); ldgX(kt + 1); }   // hide under mma
        __syncthreads();
#pragma unroll
        for (int ks = 0; ks < 4; ks++) {
            uint32_t afr[2][4];
#pragma unroll
            for (int mt = 0; mt < 2; mt++) {
                // A via trans: rows k (= ks*16 + (q>>1)*8 + r), cols d
                uint32_t ap = sW + (uint32_t)((ks * 16 + (q >> 1) * 8 + r) * XROWW
                              + (wm * 32 + mt * 16 + (q & 1) * 8) * 2);
                ldsm4t(afr[mt], ap);
            }
            uint32_t bfr[2][4];
#pragma unroll
            for (int np = 0; np < 2; np++)
                ldsm4(bfr[np], sX + boff + np * (16 * XROWX) + ks * 32);
#pragma unroll
            for (int mt = 0; mt < 2; mt++)
#pragma unroll
                for (int nt = 0; nt < 4; nt++)
                    mma_f16(acc[mt][nt], afr[mt], &bfr[nt >> 1][(nt & 1) * 2]);
        }
    }

    // epilogue: scale by inv_deg[j]*YSCALE (per column), store half2 into ysT
#pragma unroll
    for (int mt = 0; mt < 2; mt++) {
        const int d0 = dbase + wm * 32 + mt * 16 + g2;
#pragma unroll
        for (int nt = 0; nt < 4; nt++) {
            const int cl = wn * 32 + nt * 8 + t2 * 2;   // local j
            const float v0 = ivd[cl], v1 = ivd[cl + 1];
            union { __half2 h; uint32_t u; } p0, p1;
            p0.h = __floats2half2_rn(acc[mt][nt][0] * v0, acc[mt][nt][1] * v1);
            p1.h = __floats2half2_rn(acc[mt][nt][2] * v0, acc[mt][nt][3] * v1);
            *reinterpret_cast<uint32_t*>(&g_ysTh[(size_t)d0 * NN + jbase + cl]) = p0.u;
            *reinterpret_cast<uint32_t*>(&g_ysTh[(size_t)(d0 + 8) * NN + jbase + cl]) = p1.u;
        }
    }
}

// ============================================================================
// Kernel 3: out = relu( (inv_deg_i/YSCALE) * (Ah @ Yh) + bias )
// fp16 mma.sync m16n8k16: BM=128, BN=128, BK=64, 3-stage cp.async, 512 thr.
// Warp grid 4x4, warp tile 32x32. Grid 64x2 = 128 CTAs (single wave). [R4]
// ============================================================================
constexpr int BM = 128, BN = 128, BK = 64;
constexpr int STAGES = 3;
constexpr int NK = NN / BK;                   // 128
constexpr int ROWH = (BK + 8) * 2;            // 144
constexpr int TILE_B = 128 * ROWH;            // 18432
constexpr int STAGE_B = 2 * TILE_B;           // 36864
constexpr int SMEM_GEMM = STAGES * STAGE_B + 2 * BM * 4;

__global__ void __launch_bounds__(512, 1) gcn_gemm_kernel(const float* __restrict__ bias,
                                                          float* __restrict__ out) {
    extern __shared__ char smem[];
    const uint32_t sbase = smem_u32(smem);
    float* invd_s = reinterpret_cast<float*>(smem + STAGES * STAGE_B);
    float* bias_s = invd_s + BM;

    const int tid  = threadIdx.x;
    const int wid  = tid >> 5;
    const int lane = tid & 31;
    const int wm   = wid >> 2;
    const int wn   = wid & 3;
    const int mbase = blockIdx.x * BM;
    const int nbase = blockIdx.y * BN;

    if (tid < BM) {
        invd_s[tid] = g_inv_deg[mbase + tid] * (1.0f / YSCALE);
        bias_s[tid] = bias[nbase + tid];
    }

    const int g2 = lane >> 2, t2 = lane & 3;
    const int q = lane >> 3, r = lane & 7;
    const uint32_t aoff = (uint32_t)((wm * 32 + (q & 1) * 8 + r) * ROWH + (q >> 1) * 16);
    const uint32_t boff = (uint32_t)((wn * 32 + (q >> 1) * 8 + r) * ROWH + (q & 1) * 16);

    auto load_stage = [&](int st, int kt) {
        const uint32_t sA = sbase + st * STAGE_B;
        const uint32_t sB = sA + TILE_B;
        const int k0 = kt * BK;
#pragma unroll
        for (int i = 0; i < 4; i++) {
            int c = i * 512 + tid;            // 0..2047
            if (c < 1024) {
                int row = c >> 3, cq = c & 7;
                cp16(sA + row * ROWH + cq * 16,
                     g_Ah + (size_t)(mbase + row) * NN + k0 + cq * 8);
            } else {
                int c2 = c - 1024;
                int row = c2 >> 3, cq = c2 & 7;
                cp16(sB + row * ROWH + cq * 16,
                     g_ysTh + (size_t)(nbase + row) * NN + k0 + cq * 8);
            }
        }
    };

    float acc[2][4][4];
#pragma unroll
    for (int mt = 0; mt < 2; mt++)
#pragma unroll
        for (int nt = 0; nt < 4; nt++)
#pragma unroll
            for (int i = 0; i < 4; i++) acc[mt][nt][i] = 0.f;

    load_stage(0, 0); cp_commit();
    load_stage(1, 1); cp_commit();

    int st = 0;
    for (int kt = 0; kt < NK; kt++) {
        cp_wait<1>();
        __syncthreads();

        int pst = st + 2 >= STAGES ? st + 2 - STAGES : st + 2;
        if (kt + 2 < NK) load_stage(pst, kt + 2);
        cp_commit();

        const uint32_t sA = sbase + st * STAGE_B;
        const uint32_t sB = sA + TILE_B;
#pragma unroll
        for (int ks = 0; ks < 4; ks++) {
            uint32_t afr[2][4];
#pragma unroll
            for (int mt = 0; mt < 2; mt++)
                ldsm4(afr[mt], sA + aoff + mt * (16 * ROWH) + ks * 32);
            uint32_t bfr[2][4];
#pragma unroll
            for (int np = 0; np < 2; np++)
                ldsm4(bfr[np], sB + boff + np * (16 * ROWH) + ks * 32);
#pragma unroll
            for (int mt = 0; mt < 2; mt++)
#pragma unroll
                for (int nt = 0; nt < 4; nt++)
                    mma_f16(acc[mt][nt], afr[mt], &bfr[nt >> 1][(nt & 1) * 2]);
        }
        st = st + 1 >= STAGES ? 0 : st + 1;
    }

#pragma unroll
    for (int mt = 0; mt < 2; mt++) {
        const int rl = wm * 32 + mt * 16 + g2;
        const float s0 = invd_s[rl], s1 = invd_s[rl + 8];
        float* o0 = out + (size_t)(mbase + rl) * DF + nbase + wn * 32;
        float* o1 = o0 + (size_t)8 * DF;
#pragma unroll
        for (int nt = 0; nt < 4; nt++) {
            const int c = nt * 8 + t2 * 2;
            const float b0 = bias_s[wn * 32 + c], b1 = bias_s[wn * 32 + c + 1];
            float2 v0, v1;
            v0.x = fmaxf(fmaf(acc[mt][nt][0], s0, b0), 0.f);
            v0.y = fmaxf(fmaf(acc[mt][nt][1], s0, b1), 0.f);
            v1.x = fmaxf(fmaf(acc[mt][nt][2], s1, b0), 0.f);
            v1.y = fmaxf(fmaf(acc[mt][nt][3], s1, b1), 0.f);
            *reinterpret_cast<float2*>(o0 + c) = v0;
            *reinterpret_cast<float2*>(o1 + c) = v1;
        }
    }
}

// ============================================================================
// Launch
// ============================================================================
extern "C" void kernel_launch(void* const* d_in, const int* in_sizes, int n_in,
                              void* d_out, int out_size) {
    const float* x    = (const float*)d_in[0];   // [8192,256]
    const float* adj  = (const float*)d_in[1];   // [8192,8192]
    const float* W    = (const float*)d_in[2];   // [256,256]
    const float* bias = (const float*)d_in[3];   // [256]
    float* out = (float*)d_out;                  // [8192,256]

    cudaFuncSetAttribute(gcn_gemm_kernel, cudaFuncAttributeMaxDynamicSharedMemorySize,
                         SMEM_GEMM);
    cudaFuncSetAttribute(xw_tensor_kernel, cudaFuncAttributeMaxDynamicSharedMemorySize,
                         SMEM_XW);

    rowsum_kernel<<<NN, 256>>>(adj);
    dim3 xgrid(NN / 128, DF / 128);   // 64 x 2
    xw_tensor_kernel<<<xgrid, 512, SMEM_XW>>>(x, W);
    dim3 grid(NN / BM, DF / BN);      // 64 x 2
    gcn_gemm_kernel<<<grid, 512, SMEM_GEMM>>>(bias, out);
}